// round 15
// baseline (speedup 1.0000x reference)
#include <cuda_runtime.h>
#include <cuda_fp16.h>
#include <cstdint>

#define B_ 4
#define S_ 2048
#define D_ 1024
#define H_ 16
#define HD_ 64

// ---------------------------------------------------------------------------
// Scratch (device globals; all tensor-core operands are fp16)
// ---------------------------------------------------------------------------
__device__ __half g_q[B_ * H_ * S_ * HD_];     // Q pre-scaled by 1/8
__device__ __half g_k[B_ * H_ * S_ * HD_];
__device__ __half g_v[B_ * H_ * S_ * HD_];
__device__ __half g_attn[B_ * S_ * D_];
__device__ __half g_xc[B_ * S_ * D_];          // half(x)
__device__ __half g_wqkvT[3 * D_ * D_];        // W^T (K-major)
__device__ __half g_woutT[D_ * D_];

// ---------------------------------------------------------------------------
// PTX helpers
// ---------------------------------------------------------------------------
__device__ __forceinline__ uint32_t smem_u32(const void* p) {
    return (uint32_t)__cvta_generic_to_shared(p);
}
__device__ __forceinline__ void cp_async16(uint32_t dst, const void* src) {
    asm volatile("cp.async.cg.shared.global [%0], [%1], 16;" :: "r"(dst), "l"(src));
}
__device__ __forceinline__ void cp_commit() {
    asm volatile("cp.async.commit_group;" ::: "memory");
}
__device__ __forceinline__ void cp_wait1() {
    asm volatile("cp.async.wait_group 1;" ::: "memory");
}
__device__ __forceinline__ void cp_wait0() {
    asm volatile("cp.async.wait_group 0;" ::: "memory");
}
__device__ __forceinline__ void mma_f16(float* c, const uint32_t* a, const uint32_t* b) {
    asm("mma.sync.aligned.m16n8k16.row.col.f32.f16.f16.f32 "
        "{%0,%1,%2,%3}, {%4,%5,%6,%7}, {%8,%9}, {%0,%1,%2,%3};"
        : "+f"(c[0]), "+f"(c[1]), "+f"(c[2]), "+f"(c[3])
        : "r"(a[0]), "r"(a[1]), "r"(a[2]), "r"(a[3]),
          "r"(b[0]), "r"(b[1]));
}
__device__ __forceinline__ void ldsm_x4(uint32_t* r, uint32_t addr) {
    asm volatile("ldmatrix.sync.aligned.m8n8.x4.shared.b16 {%0,%1,%2,%3}, [%4];"
        : "=r"(r[0]), "=r"(r[1]), "=r"(r[2]), "=r"(r[3]) : "r"(addr));
}
__device__ __forceinline__ void ldsm_x4_t(uint32_t* r, uint32_t addr) {
    asm volatile("ldmatrix.sync.aligned.m8n8.x4.trans.shared.b16 {%0,%1,%2,%3}, [%4];"
        : "=r"(r[0]), "=r"(r[1]), "=r"(r[2]), "=r"(r[3]) : "r"(addr));
}

// ---------------------------------------------------------------------------
// Prep kernels: x -> half; W -> transposed half (K-major)
// ---------------------------------------------------------------------------
__global__ void cvt_x_kernel(const float* __restrict__ x)
{
    const long i = ((long)blockIdx.x * 256 + threadIdx.x) * 8;
    float4 v0 = *(const float4*)(x + i);
    float4 v1 = *(const float4*)(x + i + 4);
    __half2 h0 = __floats2half2_rn(v0.x, v0.y);
    __half2 h1 = __floats2half2_rn(v0.z, v0.w);
    __half2 h2 = __floats2half2_rn(v1.x, v1.y);
    __half2 h3 = __floats2half2_rn(v1.z, v1.w);
    uint4 u = make_uint4(*(uint32_t*)&h0, *(uint32_t*)&h1,
                         *(uint32_t*)&h2, *(uint32_t*)&h3);
    *(uint4*)&g_xc[i] = u;
}

__global__ void transpose_h(const float* __restrict__ W, int K, int N, int which)
{
    __shared__ __half t[32][33];
    __half* WT = which ? g_woutT : g_wqkvT;
    const int nb = blockIdx.x * 32, kb = blockIdx.y * 32;
    const int tx = threadIdx.x, ty = threadIdx.y;
#pragma unroll
    for (int j = 0; j < 32; j += 8)
        t[ty + j][tx] = __float2half_rn(W[(long)(kb + ty + j) * N + nb + tx]);
    __syncthreads();
#pragma unroll
    for (int j = 0; j < 32; j += 8)
        WT[(long)(nb + ty + j) * K + kb + tx] = t[tx][ty + j];
}

// ---------------------------------------------------------------------------
// fp16 GEMM, occupancy edition: block 128x64x32, 8 warps (4m x 2n),
// warp tile 32x32 (acc = 32 regs), m16n8k16, K-major half tiles pitch 80 B,
// 3-stage cp.async, 1 barrier/iter, __launch_bounds__(256,3) -> 3 CTAs/SM
// (24 warps; was 16). Per warp per k16: 4 LDSM + 8 mma (same ratio as before,
// 50% more concurrent chains to overlap the L1 and tensor pipes).
// MODE 0: A = g_attn, fp32 C = acc + bias.
// MODE 1: A = g_xc, scatter half(acc+bias) into g_q(*1/8)/g_k/g_v (B,H,S,HD).
// ---------------------------------------------------------------------------
#define BM 128
#define BN 64
#define BK 32
#define PITCHB 80
#define TSA_B (BM * PITCHB)              // 10240 B
#define TSB_B (BN * PITCHB)              // 5120 B
#define STAGE_B (TSA_B + TSB_B)          // 15360 B
#define NSTAGE 3
#define GEMM_SMEM_BYTES (NSTAGE * STAGE_B)   // 46080 B -> 3 CTAs/SM

template <int MODE>
__global__ __launch_bounds__(256, 3) void gemm_h(
    const float* __restrict__ bias, float* __restrict__ C,
    int M, int N, int K)
{
    extern __shared__ char smc[];
    const uint32_t sb = smem_u32(smc);

    const __half* Au = (MODE == 0) ? g_attn : g_xc;
    const __half* WT = (MODE == 0) ? g_woutT : g_wqkvT;

    const int tid = threadIdx.x;
    const int wid = tid >> 5;
    const int lane = tid & 31;
    const int g = lane >> 2;
    const int t4 = lane & 3;
    const int m0w = (wid >> 1) * 32;     // 4 m-warps
    const int n0w = (wid & 1) * 32;      // 2 n-warps
    const int bm = blockIdx.y * BM;
    const int bn = blockIdx.x * BN;

    // A x4: rows m0w+(lane&15); 16B unit selects k 0-7 / 8-15
    const uint32_t a_off = (m0w + (lane & 15)) * PITCHB + (lane >> 4) * 16;
    // B pair-x4: rows n0w+(lane&7)+((lane>>4)&1)*8; ((lane>>3)&1) selects k 16B
    const uint32_t bp_off =
        (n0w + (lane & 7) + ((lane >> 4) & 1) * 8) * PITCHB
        + ((lane >> 3) & 1) * 16;

    // loaders: A 512 chunks (2/thread), B 256 chunks (1/thread)
    auto load_tile = [&](int it) {
        const int kb = it * BK;
        const uint32_t dstA = sb + (it % NSTAGE) * STAGE_B;
        const uint32_t dstB = dstA + TSA_B;
#pragma unroll
        for (int c = 0; c < 2; ++c) {
            const int id = tid + c * 256;
            const int row = id >> 2;
            const int kc = id & 3;
            cp_async16(dstA + row * PITCHB + kc * 16,
                       Au + (long)(bm + row) * K + kb + kc * 8);
        }
        {
            const int row = tid >> 2;
            const int kc = tid & 3;
            cp_async16(dstB + row * PITCHB + kc * 16,
                       WT + (long)(bn + row) * K + kb + kc * 8);
        }
        cp_commit();
    };

    float acc[2][4][4];
#pragma unroll
    for (int ma = 0; ma < 2; ++ma)
#pragma unroll
        for (int na = 0; na < 4; ++na)
#pragma unroll
            for (int i = 0; i < 4; ++i) acc[ma][na][i] = 0.f;

    const int NIT = K / BK;
    load_tile(0);
    load_tile(1);

    for (int it = 0; it < NIT; ++it) {
        cp_wait1();
        __syncthreads();
        if (it + 2 < NIT) load_tile(it + 2);

        const uint32_t abase = sb + (it % NSTAGE) * STAGE_B + a_off;
        const uint32_t bbase = sb + (it % NSTAGE) * STAGE_B + TSA_B + bp_off;
#pragma unroll
        for (int ks = 0; ks < 2; ++ks) {
            const int kB = ks * 32;
            uint32_t af[2][4];
            uint32_t bq[2][4];
#pragma unroll
            for (int ma = 0; ma < 2; ++ma)
                ldsm_x4(af[ma], abase + ma * (16 * PITCHB) + kB);
#pragma unroll
            for (int p = 0; p < 2; ++p)
                ldsm_x4(bq[p], bbase + p * (16 * PITCHB) + kB);
#pragma unroll
            for (int ma = 0; ma < 2; ++ma)
#pragma unroll
                for (int p = 0; p < 2; ++p) {
                    mma_f16(acc[ma][2 * p],     af[ma], &bq[p][0]);
                    mma_f16(acc[ma][2 * p + 1], af[ma], &bq[p][2]);
                }
        }
    }

    // --- epilogue ------------------------------------------------------------
#pragma unroll
    for (int na = 0; na < 4; ++na) {
        const int col = bn + n0w + na * 8 + 2 * t4;
        const float2 bx = *(const float2*)&bias[col];

        if (MODE == 0) {
#pragma unroll
            for (int ma = 0; ma < 2; ++ma) {
                const long r0 = bm + m0w + ma * 16 + g;
                *(float2*)&C[r0 * N + col] =
                    make_float2(acc[ma][na][0] + bx.x, acc[ma][na][1] + bx.y);
                *(float2*)&C[(r0 + 8) * N + col] =
                    make_float2(acc[ma][na][2] + bx.x, acc[ma][na][3] + bx.y);
            }
        } else {
            const int h = col / 192;
            const int rem = col - h * 192;
            const int which = rem >> 6;
            const int d = rem & 63;
            __half* dst = (which == 0) ? g_q : (which == 1) ? g_k : g_v;
            const float sc = (which == 0) ? 0.125f : 1.0f;
#pragma unroll
            for (int ma = 0; ma < 2; ++ma) {
                const int m = bm + m0w + ma * 16 + g;
                const int b = m >> 11;
                const int s = m & (S_ - 1);
                const long base = (((long)(b * H_ + h)) * S_ + s) * HD_ + d;
                *(__half2*)&dst[base] =
                    __floats2half2_rn((acc[ma][na][0] + bx.x) * sc,
                                      (acc[ma][na][1] + bx.y) * sc);
                *(__half2*)&dst[base + 8 * HD_] =
                    __floats2half2_rn((acc[ma][na][2] + bx.x) * sc,
                                      (acc[ma][na][3] + bx.y) * sc);
            }
        }
    }
}

// ---------------------------------------------------------------------------
// fp16 flash attention (unchanged from R13 winner):
//  - V natural via cp.async, Phase-C B-frags via ldmatrix.trans
//  - K/V double-buffered, one barrier per tile
//  - in-register online softmax
// Only ceil(vlen/64) key tiles (exp underflow vs -1e6 mask is exactly 0).
// ---------------------------------------------------------------------------
#define QT 128
#define APH 72
#define APB 144                          // bytes per smem row
#define QS_B_OFF 0
#define SS_B_OFF (QT * APB)              // 18432
#define KV_OFF   (SS_B_OFF + QT * APB)   // 36864
#define KV_STAGE (2 * 64 * APB)          // K then V, 18432 B per stage
#define ATTN_SMEM_BYTES (KV_OFF + 2 * KV_STAGE)   // 73728 B

__global__ __launch_bounds__(256, 2) void attn_h(const int* __restrict__ val_lens)
{
    extern __shared__ char smc[];
    __half* Qs = (__half*)(smc + QS_B_OFF);
    __half* Ss = (__half*)(smc + SS_B_OFF);

    const int b  = blockIdx.x;           // batch fastest -> balanced waves
    const int h  = blockIdx.y;
    const int q0 = blockIdx.z * QT;
    const int vlen = val_lens[b];
    const int tid = threadIdx.x;
    const int wid = tid >> 5;
    const int lane = tid & 31;
    const int g = lane >> 2;
    const int t4 = lane & 3;
    const int m0 = wid * 16;

    const long headoff = ((long)(b * H_ + h)) * S_ * HD_;
    const __half* qbase = g_q + headoff;
    const __half* kbase = g_k + headoff;
    const __half* vbase = g_v + headoff;

    const uint32_t sb = smem_u32(smc);
    const uint32_t QS_B = sb + QS_B_OFF;
    const uint32_t SS_B = sb + SS_B_OFF;
    const uint32_t KV_B = sb + KV_OFF;

    const uint32_t qa_off = (m0 + (lane & 15)) * APB + (lane >> 4) * 16;
    const uint32_t nbp_off =
        ((lane & 7) + ((lane >> 4) & 1) * 8) * APB + ((lane >> 3) & 1) * 16;
    const uint32_t vt_off =
        ((lane & 7) + ((lane >> 3) & 1) * 8) * APB + ((lane >> 4) & 1) * 16;

    auto load_kv = [&](int kt, int buf) {
        const uint32_t dstK = KV_B + buf * KV_STAGE;
        const uint32_t dstV = dstK + 64 * APB;
#pragma unroll
        for (int c = 0; c < 2; ++c) {
            const int id = tid + c * 256;
            const int r = id >> 3;
            const int dc = id & 7;
            cp_async16(dstK + r * APB + dc * 16,
                       kbase + (long)(kt * 64 + r) * HD_ + dc * 8);
            cp_async16(dstV + r * APB + dc * 16,
                       vbase + (long)(kt * 64 + r) * HD_ + dc * 8);
        }
        cp_commit();
    };

    // Load Q tile (half, pre-scaled)
    {
        const int r = tid >> 1;
        const int c0 = (tid & 1) * 32;
        const __half* src = qbase + (long)(q0 + r) * HD_ + c0;
        __half* dst = &Qs[r * APH + c0];
#pragma unroll
        for (int j = 0; j < 32; j += 8)
            *(uint4*)(dst + j) = *(const uint4*)(src + j);
    }

    float m_lo = -3.0e38f, m_hi = -3.0e38f;
    float l_lo = 0.f, l_hi = 0.f;
    float acc_o[8][4];
#pragma unroll
    for (int na = 0; na < 8; ++na)
#pragma unroll
        for (int i = 0; i < 4; ++i) acc_o[na][i] = 0.f;

    const int ntiles = (vlen + 63) >> 6;
    load_kv(0, 0);

    for (int kt = 0; kt < ntiles; ++kt) {
        const int buf = kt & 1;
        cp_wait0();
        __syncthreads();
        if (kt + 1 < ntiles) load_kv(kt + 1, buf ^ 1);

        const uint32_t KS_B = KV_B + buf * KV_STAGE;
        const uint32_t VS_B = KS_B + 64 * APB;

        // --- Phase A: S = Q K^T ---
        float accs[8][4];
#pragma unroll
        for (int na = 0; na < 8; ++na)
#pragma unroll
            for (int i = 0; i < 4; ++i) accs[na][i] = 0.f;
#pragma unroll
        for (int ks = 0; ks < 4; ++ks) {
            const int kB = ks * 32;
            uint32_t af[4];
            ldsm_x4(af, QS_B + qa_off + kB);
#pragma unroll
            for (int p = 0; p < 4; ++p) {
                uint32_t bq[4];
                ldsm_x4(bq, KS_B + nbp_off + p * (16 * APB) + kB);
                mma_f16(accs[2 * p],     af, &bq[0]);
                mma_f16(accs[2 * p + 1], af, &bq[2]);
            }
        }

        {   // in-register masked online softmax (quad shfl reductions)
            const int cbase = kt * 64 + 2 * t4;
            float mx_lo = -3.0e38f, mx_hi = -3.0e38f;
#pragma unroll
            for (int na = 0; na < 8; ++na) {
                const int c0 = cbase + na * 8;
                if (c0 < vlen)     { mx_lo = fmaxf(mx_lo, accs[na][0]);
                                     mx_hi = fmaxf(mx_hi, accs[na][2]); }
                if (c0 + 1 < vlen) { mx_lo = fmaxf(mx_lo, accs[na][1]);
                                     mx_hi = fmaxf(mx_hi, accs[na][3]); }
            }
            mx_lo = fmaxf(mx_lo, __shfl_xor_sync(0xffffffffu, mx_lo, 1));
            mx_lo = fmaxf(mx_lo, __shfl_xor_sync(0xffffffffu, mx_lo, 2));
            mx_hi = fmaxf(mx_hi, __shfl_xor_sync(0xffffffffu, mx_hi, 1));
            mx_hi = fmaxf(mx_hi, __shfl_xor_sync(0xffffffffu, mx_hi, 2));

            const float mn_lo = fmaxf(m_lo, mx_lo);
            const float mn_hi = fmaxf(m_hi, mx_hi);
            const float al_lo = __expf(m_lo - mn_lo);
            const float al_hi = __expf(m_hi - mn_hi);

            float s_lo = 0.f, s_hi = 0.f;
#pragma unroll
            for (int na = 0; na < 8; ++na) {
                const int c0 = cbase + na * 8;
                const float p0 = (c0 < vlen)     ? __expf(accs[na][0] - mn_lo) : 0.f;
                const float p1 = (c0 + 1 < vlen) ? __expf(accs[na][1] - mn_lo) : 0.f;
                const float p2 = (c0 < vlen)     ? __expf(accs[na][2] - mn_hi) : 0.f;
                const float p3 = (c0 + 1 < vlen) ? __expf(accs[na][3] - mn_hi) : 0.f;
                s_lo += p0 + p1;
                s_hi += p2 + p3;
                *(__half2*)&Ss[(m0 + g) * APH + na * 8 + 2 * t4] =
                    __floats2half2_rn(p0, p1);
                *(__half2*)&Ss[(m0 + g + 8) * APH + na * 8 + 2 * t4] =
                    __floats2half2_rn(p2, p3);
            }
            s_lo += __shfl_xor_sync(0xffffffffu, s_lo, 1);
            s_lo += __shfl_xor_sync(0xffffffffu, s_lo, 2);
            s_hi += __shfl_xor_sync(0xffffffffu, s_hi, 1);
            s_hi += __shfl_xor_sync(0xffffffffu, s_hi, 2);

            l_lo = l_lo * al_lo + s_lo;
            l_hi = l_hi * al_hi + s_hi;
            m_lo = mn_lo;
            m_hi = mn_hi;

#pragma unroll
            for (int na = 0; na < 8; ++na) {
                acc_o[na][0] *= al_lo; acc_o[na][1] *= al_lo;
                acc_o[na][2] *= al_hi; acc_o[na][3] *= al_hi;
            }
        }
        __syncwarp();   // Ss rows are warp-private; make STS visible to LDSM

        // --- Phase C: O += P V  (V natural, trans ldmatrix) ---
#pragma unroll
        for (int ks = 0; ks < 4; ++ks) {
            uint32_t af[4];
            ldsm_x4(af, SS_B + qa_off + ks * 32);
#pragma unroll
            for (int p = 0; p < 4; ++p) {
                uint32_t bq[4];
                ldsm_x4_t(bq, VS_B + vt_off + ks * (16 * APB) + p * 32);
                mma_f16(acc_o[2 * p],     af, &bq[0]);
                mma_f16(acc_o[2 * p + 1], af, &bq[2]);
            }
        }
        // no trailing barrier: next iter's top barrier orders buffer reuse
    }

    // --- epilogue: normalize, write g_attn (half, B,S,D) ---
    {
        const float li_lo = 1.0f / l_lo;
        const float li_hi = 1.0f / l_hi;
        const long r0 = (long)b * S_ + q0 + m0 + g;
#pragma unroll
        for (int na = 0; na < 8; ++na) {
            const int col = h * HD_ + na * 8 + 2 * t4;
            *(__half2*)&g_attn[r0 * D_ + col] =
                __floats2half2_rn(acc_o[na][0] * li_lo, acc_o[na][1] * li_lo);
            *(__half2*)&g_attn[(r0 + 8) * D_ + col] =
                __floats2half2_rn(acc_o[na][2] * li_hi, acc_o[na][3] * li_hi);
        }
    }
}

// ---------------------------------------------------------------------------
// Host launcher (graph-capturable: kernel launches only, no allocs/syncs)
// ---------------------------------------------------------------------------
extern "C" void kernel_launch(void* const* d_in, const int* in_sizes, int n_in,
                              void* d_out, int out_size)
{
    const float* x        = (const float*)d_in[0];
    const float* Wqkv     = (const float*)d_in[1];
    const float* bqkv     = (const float*)d_in[2];
    const float* Wout     = (const float*)d_in[3];
    const float* bout     = (const float*)d_in[4];
    const int*   val_lens = (const int*)d_in[5];
    float* out = (float*)d_out;

    cudaFuncSetAttribute(gemm_h<1>,
                         cudaFuncAttributeMaxDynamicSharedMemorySize, GEMM_SMEM_BYTES);
    cudaFuncSetAttribute(gemm_h<0>,
                         cudaFuncAttributeMaxDynamicSharedMemorySize, GEMM_SMEM_BYTES);
    cudaFuncSetAttribute(attn_h,
                         cudaFuncAttributeMaxDynamicSharedMemorySize, ATTN_SMEM_BYTES);

    // 0) Prep: fp16 conversions/transposes
    cvt_x_kernel<<<(B_ * S_ * D_) / (256 * 8), 256>>>(x);
    {
        dim3 blk(32, 8);
        transpose_h<<<dim3((3 * D_) / 32, D_ / 32), blk>>>(Wqkv, D_, 3 * D_, 0);
        transpose_h<<<dim3(D_ / 32, D_ / 32), blk>>>(Wout, D_, D_, 1);
    }
    // 1) QKV projection -> half Q/K/V in (B,H,S,HD)
    {
        dim3 grid((3 * D_) / BN, (B_ * S_) / BM);   // 48 x 64
        gemm_h<1><<<grid, 256, GEMM_SMEM_BYTES>>>(bqkv, nullptr, B_ * S_, 3 * D_, D_);
    }
    // 2) Flash attention -> g_attn (half)
    {
        dim3 grid(B_, H_, S_ / QT);                 // batch-fastest
        attn_h<<<grid, 256, ATTN_SMEM_BYTES>>>(val_lens);
    }
    // 3) Output projection -> d_out (fp32 + bias)
    {
        dim3 grid(D_ / BN, (B_ * S_) / BM);         // 16 x 64
        gemm_h<0><<<grid, 256, GEMM_SMEM_BYTES>>>(bout, out, B_ * S_, D_, D_);
    }
}

// round 16
// speedup vs baseline: 1.0313x; 1.0313x over previous
#include <cuda_runtime.h>
#include <cuda_fp16.h>
#include <cstdint>

#define B_ 4
#define S_ 2048
#define D_ 1024
#define H_ 16
#define HD_ 64

// ---------------------------------------------------------------------------
// Scratch (device globals; all tensor-core operands are fp16)
// ---------------------------------------------------------------------------
__device__ __half g_q[B_ * H_ * S_ * HD_];     // Q pre-scaled by 1/8
__device__ __half g_k[B_ * H_ * S_ * HD_];
__device__ __half g_v[B_ * H_ * S_ * HD_];
__device__ __half g_attn[B_ * S_ * D_];
__device__ __half g_xc[B_ * S_ * D_];          // half(x)
__device__ __half g_wqkvT[3 * D_ * D_];        // W^T (K-major)
__device__ __half g_woutT[D_ * D_];

// ---------------------------------------------------------------------------
// PTX helpers
// ---------------------------------------------------------------------------
__device__ __forceinline__ uint32_t smem_u32(const void* p) {
    return (uint32_t)__cvta_generic_to_shared(p);
}
__device__ __forceinline__ void cp_async16(uint32_t dst, const void* src) {
    asm volatile("cp.async.cg.shared.global [%0], [%1], 16;" :: "r"(dst), "l"(src));
}
__device__ __forceinline__ void cp_commit() {
    asm volatile("cp.async.commit_group;" ::: "memory");
}
__device__ __forceinline__ void cp_wait1() {
    asm volatile("cp.async.wait_group 1;" ::: "memory");
}
__device__ __forceinline__ void cp_wait0() {
    asm volatile("cp.async.wait_group 0;" ::: "memory");
}
__device__ __forceinline__ void mma_f16(float* c, const uint32_t* a, const uint32_t* b) {
    asm("mma.sync.aligned.m16n8k16.row.col.f32.f16.f16.f32 "
        "{%0,%1,%2,%3}, {%4,%5,%6,%7}, {%8,%9}, {%0,%1,%2,%3};"
        : "+f"(c[0]), "+f"(c[1]), "+f"(c[2]), "+f"(c[3])
        : "r"(a[0]), "r"(a[1]), "r"(a[2]), "r"(a[3]),
          "r"(b[0]), "r"(b[1]));
}
__device__ __forceinline__ void ldsm_x4(uint32_t* r, uint32_t addr) {
    asm volatile("ldmatrix.sync.aligned.m8n8.x4.shared.b16 {%0,%1,%2,%3}, [%4];"
        : "=r"(r[0]), "=r"(r[1]), "=r"(r[2]), "=r"(r[3]) : "r"(addr));
}
__device__ __forceinline__ void ldsm_x4_t(uint32_t* r, uint32_t addr) {
    asm volatile("ldmatrix.sync.aligned.m8n8.x4.trans.shared.b16 {%0,%1,%2,%3}, [%4];"
        : "=r"(r[0]), "=r"(r[1]), "=r"(r[2]), "=r"(r[3]) : "r"(addr));
}

// ---------------------------------------------------------------------------
// Fused prep kernel (one launch):
//   blocks [0, 4096)        : x -> half (g_xc), 8 elems/thread
//   blocks [4096, 7168)     : Wqkv^T -> g_wqkvT (K-major, half)
//   blocks [7168, 8192)     : Wout^T -> g_woutT
// ---------------------------------------------------------------------------
__global__ void prep_kernel(const float* __restrict__ x,
                            const float* __restrict__ Wqkv,
                            const float* __restrict__ Wout)
{
    const int bx = blockIdx.x;
    const int tid = threadIdx.x;

    if (bx < 4096) {                       // cvt_x
        const long i = ((long)bx * 256 + tid) * 8;
        float4 v0 = *(const float4*)(x + i);
        float4 v1 = *(const float4*)(x + i + 4);
        __half2 h0 = __floats2half2_rn(v0.x, v0.y);
        __half2 h1 = __floats2half2_rn(v0.z, v0.w);
        __half2 h2 = __floats2half2_rn(v1.x, v1.y);
        __half2 h3 = __floats2half2_rn(v1.z, v1.w);
        uint4 u = make_uint4(*(uint32_t*)&h0, *(uint32_t*)&h1,
                             *(uint32_t*)&h2, *(uint32_t*)&h3);
        *(uint4*)&g_xc[i] = u;
        return;
    }

    __shared__ __half t[32][33];
    const float* W;
    __half* WT;
    int N, nb, kb;
    if (bx < 4096 + 3072) {                // Wqkv transpose: N=3072, K=1024
        const int blk = bx - 4096;
        W = Wqkv; WT = g_wqkvT; N = 3 * D_;
        nb = (blk % 96) * 32;
        kb = (blk / 96) * 32;
    } else {                               // Wout transpose: N=1024, K=1024
        const int blk = bx - 7168;
        W = Wout; WT = g_woutT; N = D_;
        nb = (blk % 32) * 32;
        kb = (blk / 32) * 32;
    }
    const int K = D_;
    const int tx = tid & 31;
    const int ty = tid >> 5;               // 0..7
#pragma unroll
    for (int j = 0; j < 32; j += 8)
        t[ty + j][tx] = __float2half_rn(W[(long)(kb + ty + j) * N + nb + tx]);
    __syncthreads();
#pragma unroll
    for (int j = 0; j < 32; j += 8)
        WT[(long)(nb + ty + j) * K + kb + tx] = t[tx][ty + j];
}

// ---------------------------------------------------------------------------
// fp16 GEMM, R13 shape (128x128x32, 8 warps 2m x 4n, warp 64x32) with
// BATCHED dual-k16 fragment loads: all 12 LDSM for both k16 steps issued
// back-to-back (MLP), then 32 mma as one burst. 3-stage cp.async,
// 1 barrier/iter, __launch_bounds__(256,2).
// MODE 0: A = g_attn, fp32 C = acc + bias.
// MODE 1: A = g_xc, scatter half(acc+bias) into g_q(*1/8)/g_k/g_v (B,H,S,HD).
// ---------------------------------------------------------------------------
#define BM 128
#define BN 128
#define BK 32
#define PITCHB 80
#define TS_B (BM * PITCHB)               // 10240 B per operand tile
#define STAGE_B (2 * TS_B)               // 20480 B
#define NSTAGE 3
#define GEMM_SMEM_BYTES (NSTAGE * STAGE_B)   // 61440 B -> 2 CTAs/SM

template <int MODE>
__global__ __launch_bounds__(256, 2) void gemm_h(
    const float* __restrict__ bias, float* __restrict__ C,
    int M, int N, int K)
{
    extern __shared__ char smc[];
    const uint32_t sb = smem_u32(smc);

    const __half* Au = (MODE == 0) ? g_attn : g_xc;
    const __half* WT = (MODE == 0) ? g_woutT : g_wqkvT;

    const int tid = threadIdx.x;
    const int wid = tid >> 5;
    const int lane = tid & 31;
    const int g = lane >> 2;
    const int t4 = lane & 3;
    const int m0w = (wid >> 2) * 64;
    const int n0w = (wid & 3) * 32;
    const int bm = blockIdx.y * BM;
    const int bn = blockIdx.x * BN;

    const uint32_t a_off = (m0w + (lane & 15)) * PITCHB + (lane >> 4) * 16;
    const uint32_t bp_off =
        (n0w + (lane & 7) + ((lane >> 4) & 1) * 8) * PITCHB
        + ((lane >> 3) & 1) * 16;

    auto load_tile = [&](int it) {
        const int kb = it * BK;
        const uint32_t dstA = sb + (it % NSTAGE) * STAGE_B;
        const uint32_t dstB = dstA + TS_B;
#pragma unroll
        for (int c = 0; c < 2; ++c) {
            const int id = tid + c * 256;
            const int row = id >> 2;
            const int kc = id & 3;
            cp_async16(dstA + row * PITCHB + kc * 16,
                       Au + (long)(bm + row) * K + kb + kc * 8);
            cp_async16(dstB + row * PITCHB + kc * 16,
                       WT + (long)(bn + row) * K + kb + kc * 8);
        }
        cp_commit();
    };

    float acc[4][4][4];
#pragma unroll
    for (int ma = 0; ma < 4; ++ma)
#pragma unroll
        for (int na = 0; na < 4; ++na)
#pragma unroll
            for (int i = 0; i < 4; ++i) acc[ma][na][i] = 0.f;

    const int NIT = K / BK;
    load_tile(0);
    load_tile(1);

    for (int it = 0; it < NIT; ++it) {
        cp_wait1();
        __syncthreads();
        if (it + 2 < NIT) load_tile(it + 2);

        const uint32_t abase = sb + (it % NSTAGE) * STAGE_B + a_off;
        const uint32_t bbase = sb + (it % NSTAGE) * STAGE_B + TS_B + bp_off;

        // --- batched fragment loads: 12 LDSM back-to-back ---
        uint32_t af[2][4][4];
        uint32_t bq[2][2][4];
#pragma unroll
        for (int ks = 0; ks < 2; ++ks) {
            const int kB = ks * 32;
#pragma unroll
            for (int ma = 0; ma < 4; ++ma)
                ldsm_x4(af[ks][ma], abase + ma * (16 * PITCHB) + kB);
#pragma unroll
            for (int p = 0; p < 2; ++p)
                ldsm_x4(bq[ks][p], bbase + p * (16 * PITCHB) + kB);
        }
        // --- 32 mma burst ---
#pragma unroll
        for (int ks = 0; ks < 2; ++ks)
#pragma unroll
            for (int ma = 0; ma < 4; ++ma)
#pragma unroll
                for (int p = 0; p < 2; ++p) {
                    mma_f16(acc[ma][2 * p],     af[ks][ma], &bq[ks][p][0]);
                    mma_f16(acc[ma][2 * p + 1], af[ks][ma], &bq[ks][p][2]);
                }
    }

    // --- epilogue ------------------------------------------------------------
#pragma unroll
    for (int na = 0; na < 4; ++na) {
        const int col = bn + n0w + na * 8 + 2 * t4;
        const float2 bx = *(const float2*)&bias[col];

        if (MODE == 0) {
#pragma unroll
            for (int ma = 0; ma < 4; ++ma) {
                const long r0 = bm + m0w + ma * 16 + g;
                *(float2*)&C[r0 * N + col] =
                    make_float2(acc[ma][na][0] + bx.x, acc[ma][na][1] + bx.y);
                *(float2*)&C[(r0 + 8) * N + col] =
                    make_float2(acc[ma][na][2] + bx.x, acc[ma][na][3] + bx.y);
            }
        } else {
            const int h = col / 192;
            const int rem = col - h * 192;
            const int which = rem >> 6;
            const int d = rem & 63;
            __half* dst = (which == 0) ? g_q : (which == 1) ? g_k : g_v;
            const float sc = (which == 0) ? 0.125f : 1.0f;
#pragma unroll
            for (int ma = 0; ma < 4; ++ma) {
                const int m = bm + m0w + ma * 16 + g;
                const int b = m >> 11;
                const int s = m & (S_ - 1);
                const long base = (((long)(b * H_ + h)) * S_ + s) * HD_ + d;
                *(__half2*)&dst[base] =
                    __floats2half2_rn((acc[ma][na][0] + bx.x) * sc,
                                      (acc[ma][na][1] + bx.y) * sc);
                *(__half2*)&dst[base + 8 * HD_] =
                    __floats2half2_rn((acc[ma][na][2] + bx.x) * sc,
                                      (acc[ma][na][3] + bx.y) * sc);
            }
        }
    }
}

// ---------------------------------------------------------------------------
// fp16 flash attention (unchanged R13 winner):
//  - V natural via cp.async, Phase-C B-frags via ldmatrix.trans
//  - K/V double-buffered, one barrier per tile
//  - in-register online softmax
// Only ceil(vlen/64) key tiles (exp underflow vs -1e6 mask is exactly 0).
// ---------------------------------------------------------------------------
#define QT 128
#define APH 72
#define APB 144                          // bytes per smem row
#define QS_B_OFF 0
#define SS_B_OFF (QT * APB)              // 18432
#define KV_OFF   (SS_B_OFF + QT * APB)   // 36864
#define KV_STAGE (2 * 64 * APB)          // K then V, 18432 B per stage
#define ATTN_SMEM_BYTES (KV_OFF + 2 * KV_STAGE)   // 73728 B

__global__ __launch_bounds__(256, 2) void attn_h(const int* __restrict__ val_lens)
{
    extern __shared__ char smc[];
    __half* Qs = (__half*)(smc + QS_B_OFF);
    __half* Ss = (__half*)(smc + SS_B_OFF);

    const int b  = blockIdx.x;           // batch fastest -> balanced waves
    const int h  = blockIdx.y;
    const int q0 = blockIdx.z * QT;
    const int vlen = val_lens[b];
    const int tid = threadIdx.x;
    const int wid = tid >> 5;
    const int lane = tid & 31;
    const int g = lane >> 2;
    const int t4 = lane & 3;
    const int m0 = wid * 16;

    const long headoff = ((long)(b * H_ + h)) * S_ * HD_;
    const __half* qbase = g_q + headoff;
    const __half* kbase = g_k + headoff;
    const __half* vbase = g_v + headoff;

    const uint32_t sb = smem_u32(smc);
    const uint32_t QS_B = sb + QS_B_OFF;
    const uint32_t SS_B = sb + SS_B_OFF;
    const uint32_t KV_B = sb + KV_OFF;

    const uint32_t qa_off = (m0 + (lane & 15)) * APB + (lane >> 4) * 16;
    const uint32_t nbp_off =
        ((lane & 7) + ((lane >> 4) & 1) * 8) * APB + ((lane >> 3) & 1) * 16;
    const uint32_t vt_off =
        ((lane & 7) + ((lane >> 3) & 1) * 8) * APB + ((lane >> 4) & 1) * 16;

    auto load_kv = [&](int kt, int buf) {
        const uint32_t dstK = KV_B + buf * KV_STAGE;
        const uint32_t dstV = dstK + 64 * APB;
#pragma unroll
        for (int c = 0; c < 2; ++c) {
            const int id = tid + c * 256;
            const int r = id >> 3;
            const int dc = id & 7;
            cp_async16(dstK + r * APB + dc * 16,
                       kbase + (long)(kt * 64 + r) * HD_ + dc * 8);
            cp_async16(dstV + r * APB + dc * 16,
                       vbase + (long)(kt * 64 + r) * HD_ + dc * 8);
        }
        cp_commit();
    };

    // Load Q tile (half, pre-scaled)
    {
        const int r = tid >> 1;
        const int c0 = (tid & 1) * 32;
        const __half* src = qbase + (long)(q0 + r) * HD_ + c0;
        __half* dst = &Qs[r * APH + c0];
#pragma unroll
        for (int j = 0; j < 32; j += 8)
            *(uint4*)(dst + j) = *(const uint4*)(src + j);
    }

    float m_lo = -3.0e38f, m_hi = -3.0e38f;
    float l_lo = 0.f, l_hi = 0.f;
    float acc_o[8][4];
#pragma unroll
    for (int na = 0; na < 8; ++na)
#pragma unroll
        for (int i = 0; i < 4; ++i) acc_o[na][i] = 0.f;

    const int ntiles = (vlen + 63) >> 6;
    load_kv(0, 0);

    for (int kt = 0; kt < ntiles; ++kt) {
        const int buf = kt & 1;
        cp_wait0();
        __syncthreads();
        if (kt + 1 < ntiles) load_kv(kt + 1, buf ^ 1);

        const uint32_t KS_B = KV_B + buf * KV_STAGE;
        const uint32_t VS_B = KS_B + 64 * APB;

        // --- Phase A: S = Q K^T ---
        float accs[8][4];
#pragma unroll
        for (int na = 0; na < 8; ++na)
#pragma unroll
            for (int i = 0; i < 4; ++i) accs[na][i] = 0.f;
#pragma unroll
        for (int ks = 0; ks < 4; ++ks) {
            const int kB = ks * 32;
            uint32_t af[4];
            ldsm_x4(af, QS_B + qa_off + kB);
#pragma unroll
            for (int p = 0; p < 4; ++p) {
                uint32_t bq[4];
                ldsm_x4(bq, KS_B + nbp_off + p * (16 * APB) + kB);
                mma_f16(accs[2 * p],     af, &bq[0]);
                mma_f16(accs[2 * p + 1], af, &bq[2]);
            }
        }

        {   // in-register masked online softmax (quad shfl reductions)
            const int cbase = kt * 64 + 2 * t4;
            float mx_lo = -3.0e38f, mx_hi = -3.0e38f;
#pragma unroll
            for (int na = 0; na < 8; ++na) {
                const int c0 = cbase + na * 8;
                if (c0 < vlen)     { mx_lo = fmaxf(mx_lo, accs[na][0]);
                                     mx_hi = fmaxf(mx_hi, accs[na][2]); }
                if (c0 + 1 < vlen) { mx_lo = fmaxf(mx_lo, accs[na][1]);
                                     mx_hi = fmaxf(mx_hi, accs[na][3]); }
            }
            mx_lo = fmaxf(mx_lo, __shfl_xor_sync(0xffffffffu, mx_lo, 1));
            mx_lo = fmaxf(mx_lo, __shfl_xor_sync(0xffffffffu, mx_lo, 2));
            mx_hi = fmaxf(mx_hi, __shfl_xor_sync(0xffffffffu, mx_hi, 1));
            mx_hi = fmaxf(mx_hi, __shfl_xor_sync(0xffffffffu, mx_hi, 2));

            const float mn_lo = fmaxf(m_lo, mx_lo);
            const float mn_hi = fmaxf(m_hi, mx_hi);
            const float al_lo = __expf(m_lo - mn_lo);
            const float al_hi = __expf(m_hi - mn_hi);

            float s_lo = 0.f, s_hi = 0.f;
#pragma unroll
            for (int na = 0; na < 8; ++na) {
                const int c0 = cbase + na * 8;
                const float p0 = (c0 < vlen)     ? __expf(accs[na][0] - mn_lo) : 0.f;
                const float p1 = (c0 + 1 < vlen) ? __expf(accs[na][1] - mn_lo) : 0.f;
                const float p2 = (c0 < vlen)     ? __expf(accs[na][2] - mn_hi) : 0.f;
                const float p3 = (c0 + 1 < vlen) ? __expf(accs[na][3] - mn_hi) : 0.f;
                s_lo += p0 + p1;
                s_hi += p2 + p3;
                *(__half2*)&Ss[(m0 + g) * APH + na * 8 + 2 * t4] =
                    __floats2half2_rn(p0, p1);
                *(__half2*)&Ss[(m0 + g + 8) * APH + na * 8 + 2 * t4] =
                    __floats2half2_rn(p2, p3);
            }
            s_lo += __shfl_xor_sync(0xffffffffu, s_lo, 1);
            s_lo += __shfl_xor_sync(0xffffffffu, s_lo, 2);
            s_hi += __shfl_xor_sync(0xffffffffu, s_hi, 1);
            s_hi += __shfl_xor_sync(0xffffffffu, s_hi, 2);

            l_lo = l_lo * al_lo + s_lo;
            l_hi = l_hi * al_hi + s_hi;
            m_lo = mn_lo;
            m_hi = mn_hi;

#pragma unroll
            for (int na = 0; na < 8; ++na) {
                acc_o[na][0] *= al_lo; acc_o[na][1] *= al_lo;
                acc_o[na][2] *= al_hi; acc_o[na][3] *= al_hi;
            }
        }
        __syncwarp();   // Ss rows are warp-private; make STS visible to LDSM

        // --- Phase C: O += P V  (V natural, trans ldmatrix) ---
#pragma unroll
        for (int ks = 0; ks < 4; ++ks) {
            uint32_t af[4];
            ldsm_x4(af, SS_B + qa_off + ks * 32);
#pragma unroll
            for (int p = 0; p < 4; ++p) {
                uint32_t bq[4];
                ldsm_x4_t(bq, VS_B + vt_off + ks * (16 * APB) + p * 32);
                mma_f16(acc_o[2 * p],     af, &bq[0]);
                mma_f16(acc_o[2 * p + 1], af, &bq[2]);
            }
        }
        // no trailing barrier: next iter's top barrier orders buffer reuse
    }

    // --- epilogue: normalize, write g_attn (half, B,S,D) ---
    {
        const float li_lo = 1.0f / l_lo;
        const float li_hi = 1.0f / l_hi;
        const long r0 = (long)b * S_ + q0 + m0 + g;
#pragma unroll
        for (int na = 0; na < 8; ++na) {
            const int col = h * HD_ + na * 8 + 2 * t4;
            *(__half2*)&g_attn[r0 * D_ + col] =
                __floats2half2_rn(acc_o[na][0] * li_lo, acc_o[na][1] * li_lo);
            *(__half2*)&g_attn[(r0 + 8) * D_ + col] =
                __floats2half2_rn(acc_o[na][2] * li_hi, acc_o[na][3] * li_hi);
        }
    }
}

// ---------------------------------------------------------------------------
// Host launcher (graph-capturable: kernel launches only, no allocs/syncs)
// ---------------------------------------------------------------------------
extern "C" void kernel_launch(void* const* d_in, const int* in_sizes, int n_in,
                              void* d_out, int out_size)
{
    const float* x        = (const float*)d_in[0];
    const float* Wqkv     = (const float*)d_in[1];
    const float* bqkv     = (const float*)d_in[2];
    const float* Wout     = (const float*)d_in[3];
    const float* bout     = (const float*)d_in[4];
    const int*   val_lens = (const int*)d_in[5];
    float* out = (float*)d_out;

    cudaFuncSetAttribute(gemm_h<1>,
                         cudaFuncAttributeMaxDynamicSharedMemorySize, GEMM_SMEM_BYTES);
    cudaFuncSetAttribute(gemm_h<0>,
                         cudaFuncAttributeMaxDynamicSharedMemorySize, GEMM_SMEM_BYTES);
    cudaFuncSetAttribute(attn_h,
                         cudaFuncAttributeMaxDynamicSharedMemorySize, ATTN_SMEM_BYTES);

    // 0) Fused prep: x->half + both weight transposes, one launch
    prep_kernel<<<8192, 256>>>(x, Wqkv, Wout);

    // 1) QKV projection -> half Q/K/V in (B,H,S,HD)
    {
        dim3 grid((3 * D_) / BN, (B_ * S_) / BM);   // 24 x 64
        gemm_h<1><<<grid, 256, GEMM_SMEM_BYTES>>>(bqkv, nullptr, B_ * S_, 3 * D_, D_);
    }
    // 2) Flash attention -> g_attn (half)
    {
        dim3 grid(B_, H_, S_ / QT);                 // batch-fastest
        attn_h<<<grid, 256, ATTN_SMEM_BYTES>>>(val_lens);
    }
    // 3) Output projection -> d_out (fp32 + bias)
    {
        dim3 grid(D_ / BN, (B_ * S_) / BM);         // 8 x 64
        gemm_h<0><<<grid, 256, GEMM_SMEM_BYTES>>>(bout, out, B_ * S_, D_, D_);
    }
}

// round 17
// speedup vs baseline: 1.0531x; 1.0211x over previous
#include <cuda_runtime.h>
#include <cuda_fp16.h>
#include <cstdint>

#define B_ 4
#define S_ 2048
#define D_ 1024
#define H_ 16
#define HD_ 64

// ---------------------------------------------------------------------------
// Scratch (device globals; all tensor-core operands are fp16)
// ---------------------------------------------------------------------------
__device__ __half g_q[B_ * H_ * S_ * HD_];     // Q pre-scaled by 1/8
__device__ __half g_k[B_ * H_ * S_ * HD_];
__device__ __half g_v[B_ * H_ * S_ * HD_];
__device__ __half g_attn[B_ * S_ * D_];
__device__ __half g_xc[B_ * S_ * D_];          // half(x)
__device__ __half g_wqkvT[3 * D_ * D_];        // W^T (K-major)
__device__ __half g_woutT[D_ * D_];

// ---------------------------------------------------------------------------
// PTX helpers
// ---------------------------------------------------------------------------
__device__ __forceinline__ uint32_t smem_u32(const void* p) {
    return (uint32_t)__cvta_generic_to_shared(p);
}
__device__ __forceinline__ void cp_async16(uint32_t dst, const void* src) {
    asm volatile("cp.async.cg.shared.global [%0], [%1], 16;" :: "r"(dst), "l"(src));
}
__device__ __forceinline__ void cp_commit() {
    asm volatile("cp.async.commit_group;" ::: "memory");
}
__device__ __forceinline__ void cp_wait2() {
    asm volatile("cp.async.wait_group 2;" ::: "memory");
}
__device__ __forceinline__ void cp_wait0() {
    asm volatile("cp.async.wait_group 0;" ::: "memory");
}
__device__ __forceinline__ void mma_f16(float* c, const uint32_t* a, const uint32_t* b) {
    asm("mma.sync.aligned.m16n8k16.row.col.f32.f16.f16.f32 "
        "{%0,%1,%2,%3}, {%4,%5,%6,%7}, {%8,%9}, {%0,%1,%2,%3};"
        : "+f"(c[0]), "+f"(c[1]), "+f"(c[2]), "+f"(c[3])
        : "r"(a[0]), "r"(a[1]), "r"(a[2]), "r"(a[3]),
          "r"(b[0]), "r"(b[1]));
}
__device__ __forceinline__ void ldsm_x4(uint32_t* r, uint32_t addr) {
    asm volatile("ldmatrix.sync.aligned.m8n8.x4.shared.b16 {%0,%1,%2,%3}, [%4];"
        : "=r"(r[0]), "=r"(r[1]), "=r"(r[2]), "=r"(r[3]) : "r"(addr));
}
__device__ __forceinline__ void ldsm_x4_t(uint32_t* r, uint32_t addr) {
    asm volatile("ldmatrix.sync.aligned.m8n8.x4.trans.shared.b16 {%0,%1,%2,%3}, [%4];"
        : "=r"(r[0]), "=r"(r[1]), "=r"(r[2]), "=r"(r[3]) : "r"(addr));
}

// ---------------------------------------------------------------------------
// Fused prep kernel (one launch):
//   blocks [0, 4096)        : x -> half (g_xc), 8 elems/thread
//   blocks [4096, 7168)     : Wqkv^T -> g_wqkvT (K-major, half)
//   blocks [7168, 8192)     : Wout^T -> g_woutT
// ---------------------------------------------------------------------------
__global__ void prep_kernel(const float* __restrict__ x,
                            const float* __restrict__ Wqkv,
                            const float* __restrict__ Wout)
{
    const int bx = blockIdx.x;
    const int tid = threadIdx.x;

    if (bx < 4096) {                       // cvt_x
        const long i = ((long)bx * 256 + tid) * 8;
        float4 v0 = *(const float4*)(x + i);
        float4 v1 = *(const float4*)(x + i + 4);
        __half2 h0 = __floats2half2_rn(v0.x, v0.y);
        __half2 h1 = __floats2half2_rn(v0.z, v0.w);
        __half2 h2 = __floats2half2_rn(v1.x, v1.y);
        __half2 h3 = __floats2half2_rn(v1.z, v1.w);
        uint4 u = make_uint4(*(uint32_t*)&h0, *(uint32_t*)&h1,
                             *(uint32_t*)&h2, *(uint32_t*)&h3);
        *(uint4*)&g_xc[i] = u;
        return;
    }

    __shared__ __half t[32][33];
    const float* W;
    __half* WT;
    int N, nb, kb;
    if (bx < 4096 + 3072) {                // Wqkv transpose: N=3072, K=1024
        const int blk = bx - 4096;
        W = Wqkv; WT = g_wqkvT; N = 3 * D_;
        nb = (blk % 96) * 32;
        kb = (blk / 96) * 32;
    } else {                               // Wout transpose: N=1024, K=1024
        const int blk = bx - 7168;
        W = Wout; WT = g_woutT; N = D_;
        nb = (blk % 32) * 32;
        kb = (blk / 32) * 32;
    }
    const int K = D_;
    const int tx = tid & 31;
    const int ty = tid >> 5;               // 0..7
#pragma unroll
    for (int j = 0; j < 32; j += 8)
        t[ty + j][tx] = __float2half_rn(W[(long)(kb + ty + j) * N + nb + tx]);
    __syncthreads();
#pragma unroll
    for (int j = 0; j < 32; j += 8)
        WT[(long)(nb + ty + j) * K + kb + tx] = t[tx][ty + j];
}

// ---------------------------------------------------------------------------
// fp16 GEMM, R13 per-ks inner loop (proven fastest), 4-stage cp.async ring
// (prefetch distance 3, wait_group 2), block 128x128x32, 8 warps (2m x 4n),
// warp 64x32, m16n8k16, K-major half tiles pitch 80 B, 1 barrier/iter.
// MODE 0: A = g_attn, fp32 C = acc + bias.
// MODE 1: A = g_xc, scatter half(acc+bias) into g_q(*1/8)/g_k/g_v (B,H,S,HD).
// ---------------------------------------------------------------------------
#define BM 128
#define BN 128
#define BK 32
#define PITCHB 80
#define TS_B (BM * PITCHB)               // 10240 B per operand tile
#define STAGE_B (2 * TS_B)               // 20480 B
#define NSTAGE 4
#define GEMM_SMEM_BYTES (NSTAGE * STAGE_B)   // 81920 B -> 2 CTAs/SM (163.8 KB)

template <int MODE>
__global__ __launch_bounds__(256, 2) void gemm_h(
    const float* __restrict__ bias, float* __restrict__ C,
    int M, int N, int K)
{
    extern __shared__ char smc[];
    const uint32_t sb = smem_u32(smc);

    const __half* Au = (MODE == 0) ? g_attn : g_xc;
    const __half* WT = (MODE == 0) ? g_woutT : g_wqkvT;

    const int tid = threadIdx.x;
    const int wid = tid >> 5;
    const int lane = tid & 31;
    const int g = lane >> 2;
    const int t4 = lane & 3;
    const int m0w = (wid >> 2) * 64;
    const int n0w = (wid & 3) * 32;
    const int bm = blockIdx.y * BM;
    const int bn = blockIdx.x * BN;

    const uint32_t a_off = (m0w + (lane & 15)) * PITCHB + (lane >> 4) * 16;
    const uint32_t bp_off =
        (n0w + (lane & 7) + ((lane >> 4) & 1) * 8) * PITCHB
        + ((lane >> 3) & 1) * 16;

    auto load_tile = [&](int it) {
        const int kb = it * BK;
        const uint32_t dstA = sb + (it % NSTAGE) * STAGE_B;
        const uint32_t dstB = dstA + TS_B;
#pragma unroll
        for (int c = 0; c < 2; ++c) {
            const int id = tid + c * 256;
            const int row = id >> 2;
            const int kc = id & 3;
            cp_async16(dstA + row * PITCHB + kc * 16,
                       Au + (long)(bm + row) * K + kb + kc * 8);
            cp_async16(dstB + row * PITCHB + kc * 16,
                       WT + (long)(bn + row) * K + kb + kc * 8);
        }
        cp_commit();
    };

    float acc[4][4][4];
#pragma unroll
    for (int ma = 0; ma < 4; ++ma)
#pragma unroll
        for (int na = 0; na < 4; ++na)
#pragma unroll
            for (int i = 0; i < 4; ++i) acc[ma][na][i] = 0.f;

    const int NIT = K / BK;
    load_tile(0);
    load_tile(1);
    load_tile(2);

    for (int it = 0; it < NIT; ++it) {
        cp_wait2();          // stage it%NSTAGE complete (3 groups max in flight)
        __syncthreads();     // + readers of stage (it+3)%NSTAGE finished it-1
        if (it + 3 < NIT) load_tile(it + 3);

        const uint32_t abase = sb + (it % NSTAGE) * STAGE_B + a_off;
        const uint32_t bbase = sb + (it % NSTAGE) * STAGE_B + TS_B + bp_off;
#pragma unroll
        for (int ks = 0; ks < 2; ++ks) {
            const int kB = ks * 32;
            uint32_t af[4][4];
            uint32_t bq[2][4];
#pragma unroll
            for (int ma = 0; ma < 4; ++ma)
                ldsm_x4(af[ma], abase + ma * (16 * PITCHB) + kB);
#pragma unroll
            for (int p = 0; p < 2; ++p)
                ldsm_x4(bq[p], bbase + p * (16 * PITCHB) + kB);
#pragma unroll
            for (int ma = 0; ma < 4; ++ma)
#pragma unroll
                for (int p = 0; p < 2; ++p) {
                    mma_f16(acc[ma][2 * p],     af[ma], &bq[p][0]);
                    mma_f16(acc[ma][2 * p + 1], af[ma], &bq[p][2]);
                }
        }
    }

    // --- epilogue ------------------------------------------------------------
#pragma unroll
    for (int na = 0; na < 4; ++na) {
        const int col = bn + n0w + na * 8 + 2 * t4;
        const float2 bx = *(const float2*)&bias[col];

        if (MODE == 0) {
#pragma unroll
            for (int ma = 0; ma < 4; ++ma) {
                const long r0 = bm + m0w + ma * 16 + g;
                *(float2*)&C[r0 * N + col] =
                    make_float2(acc[ma][na][0] + bx.x, acc[ma][na][1] + bx.y);
                *(float2*)&C[(r0 + 8) * N + col] =
                    make_float2(acc[ma][na][2] + bx.x, acc[ma][na][3] + bx.y);
            }
        } else {
            const int h = col / 192;
            const int rem = col - h * 192;
            const int which = rem >> 6;
            const int d = rem & 63;
            __half* dst = (which == 0) ? g_q : (which == 1) ? g_k : g_v;
            const float sc = (which == 0) ? 0.125f : 1.0f;
#pragma unroll
            for (int ma = 0; ma < 4; ++ma) {
                const int m = bm + m0w + ma * 16 + g;
                const int b = m >> 11;
                const int s = m & (S_ - 1);
                const long base = (((long)(b * H_ + h)) * S_ + s) * HD_ + d;
                *(__half2*)&dst[base] =
                    __floats2half2_rn((acc[ma][na][0] + bx.x) * sc,
                                      (acc[ma][na][1] + bx.y) * sc);
                *(__half2*)&dst[base + 8 * HD_] =
                    __floats2half2_rn((acc[ma][na][2] + bx.x) * sc,
                                      (acc[ma][na][3] + bx.y) * sc);
            }
        }
    }
}

// ---------------------------------------------------------------------------
// fp16 flash attention (unchanged R13 winner):
//  - V natural via cp.async, Phase-C B-frags via ldmatrix.trans
//  - K/V double-buffered, one barrier per tile
//  - in-register online softmax
// Only ceil(vlen/64) key tiles (exp underflow vs -1e6 mask is exactly 0).
// ---------------------------------------------------------------------------
#define QT 128
#define APH 72
#define APB 144                          // bytes per smem row
#define QS_B_OFF 0
#define SS_B_OFF (QT * APB)              // 18432
#define KV_OFF   (SS_B_OFF + QT * APB)   // 36864
#define KV_STAGE (2 * 64 * APB)          // K then V, 18432 B per stage
#define ATTN_SMEM_BYTES (KV_OFF + 2 * KV_STAGE)   // 73728 B

__global__ __launch_bounds__(256, 2) void attn_h(const int* __restrict__ val_lens)
{
    extern __shared__ char smc[];
    __half* Qs = (__half*)(smc + QS_B_OFF);
    __half* Ss = (__half*)(smc + SS_B_OFF);

    const int b  = blockIdx.x;           // batch fastest -> balanced waves
    const int h  = blockIdx.y;
    const int q0 = blockIdx.z * QT;
    const int vlen = val_lens[b];
    const int tid = threadIdx.x;
    const int wid = tid >> 5;
    const int lane = tid & 31;
    const int g = lane >> 2;
    const int t4 = lane & 3;
    const int m0 = wid * 16;

    const long headoff = ((long)(b * H_ + h)) * S_ * HD_;
    const __half* qbase = g_q + headoff;
    const __half* kbase = g_k + headoff;
    const __half* vbase = g_v + headoff;

    const uint32_t sb = smem_u32(smc);
    const uint32_t QS_B = sb + QS_B_OFF;
    const uint32_t SS_B = sb + SS_B_OFF;
    const uint32_t KV_B = sb + KV_OFF;

    const uint32_t qa_off = (m0 + (lane & 15)) * APB + (lane >> 4) * 16;
    const uint32_t nbp_off =
        ((lane & 7) + ((lane >> 4) & 1) * 8) * APB + ((lane >> 3) & 1) * 16;
    const uint32_t vt_off =
        ((lane & 7) + ((lane >> 3) & 1) * 8) * APB + ((lane >> 4) & 1) * 16;

    auto load_kv = [&](int kt, int buf) {
        const uint32_t dstK = KV_B + buf * KV_STAGE;
        const uint32_t dstV = dstK + 64 * APB;
#pragma unroll
        for (int c = 0; c < 2; ++c) {
            const int id = tid + c * 256;
            const int r = id >> 3;
            const int dc = id & 7;
            cp_async16(dstK + r * APB + dc * 16,
                       kbase + (long)(kt * 64 + r) * HD_ + dc * 8);
            cp_async16(dstV + r * APB + dc * 16,
                       vbase + (long)(kt * 64 + r) * HD_ + dc * 8);
        }
        cp_commit();
    };

    // Load Q tile (half, pre-scaled)
    {
        const int r = tid >> 1;
        const int c0 = (tid & 1) * 32;
        const __half* src = qbase + (long)(q0 + r) * HD_ + c0;
        __half* dst = &Qs[r * APH + c0];
#pragma unroll
        for (int j = 0; j < 32; j += 8)
            *(uint4*)(dst + j) = *(const uint4*)(src + j);
    }

    float m_lo = -3.0e38f, m_hi = -3.0e38f;
    float l_lo = 0.f, l_hi = 0.f;
    float acc_o[8][4];
#pragma unroll
    for (int na = 0; na < 8; ++na)
#pragma unroll
        for (int i = 0; i < 4; ++i) acc_o[na][i] = 0.f;

    const int ntiles = (vlen + 63) >> 6;
    load_kv(0, 0);

    for (int kt = 0; kt < ntiles; ++kt) {
        const int buf = kt & 1;
        cp_wait0();
        __syncthreads();
        if (kt + 1 < ntiles) load_kv(kt + 1, buf ^ 1);

        const uint32_t KS_B = KV_B + buf * KV_STAGE;
        const uint32_t VS_B = KS_B + 64 * APB;

        // --- Phase A: S = Q K^T ---
        float accs[8][4];
#pragma unroll
        for (int na = 0; na < 8; ++na)
#pragma unroll
            for (int i = 0; i < 4; ++i) accs[na][i] = 0.f;
#pragma unroll
        for (int ks = 0; ks < 4; ++ks) {
            const int kB = ks * 32;
            uint32_t af[4];
            ldsm_x4(af, QS_B + qa_off + kB);
#pragma unroll
            for (int p = 0; p < 4; ++p) {
                uint32_t bq[4];
                ldsm_x4(bq, KS_B + nbp_off + p * (16 * APB) + kB);
                mma_f16(accs[2 * p],     af, &bq[0]);
                mma_f16(accs[2 * p + 1], af, &bq[2]);
            }
        }

        {   // in-register masked online softmax (quad shfl reductions)
            const int cbase = kt * 64 + 2 * t4;
            float mx_lo = -3.0e38f, mx_hi = -3.0e38f;
#pragma unroll
            for (int na = 0; na < 8; ++na) {
                const int c0 = cbase + na * 8;
                if (c0 < vlen)     { mx_lo = fmaxf(mx_lo, accs[na][0]);
                                     mx_hi = fmaxf(mx_hi, accs[na][2]); }
                if (c0 + 1 < vlen) { mx_lo = fmaxf(mx_lo, accs[na][1]);
                                     mx_hi = fmaxf(mx_hi, accs[na][3]); }
            }
            mx_lo = fmaxf(mx_lo, __shfl_xor_sync(0xffffffffu, mx_lo, 1));
            mx_lo = fmaxf(mx_lo, __shfl_xor_sync(0xffffffffu, mx_lo, 2));
            mx_hi = fmaxf(mx_hi, __shfl_xor_sync(0xffffffffu, mx_hi, 1));
            mx_hi = fmaxf(mx_hi, __shfl_xor_sync(0xffffffffu, mx_hi, 2));

            const float mn_lo = fmaxf(m_lo, mx_lo);
            const float mn_hi = fmaxf(m_hi, mx_hi);
            const float al_lo = __expf(m_lo - mn_lo);
            const float al_hi = __expf(m_hi - mn_hi);

            float s_lo = 0.f, s_hi = 0.f;
#pragma unroll
            for (int na = 0; na < 8; ++na) {
                const int c0 = cbase + na * 8;
                const float p0 = (c0 < vlen)     ? __expf(accs[na][0] - mn_lo) : 0.f;
                const float p1 = (c0 + 1 < vlen) ? __expf(accs[na][1] - mn_lo) : 0.f;
                const float p2 = (c0 < vlen)     ? __expf(accs[na][2] - mn_hi) : 0.f;
                const float p3 = (c0 + 1 < vlen) ? __expf(accs[na][3] - mn_hi) : 0.f;
                s_lo += p0 + p1;
                s_hi += p2 + p3;
                *(__half2*)&Ss[(m0 + g) * APH + na * 8 + 2 * t4] =
                    __floats2half2_rn(p0, p1);
                *(__half2*)&Ss[(m0 + g + 8) * APH + na * 8 + 2 * t4] =
                    __floats2half2_rn(p2, p3);
            }
            s_lo += __shfl_xor_sync(0xffffffffu, s_lo, 1);
            s_lo += __shfl_xor_sync(0xffffffffu, s_lo, 2);
            s_hi += __shfl_xor_sync(0xffffffffu, s_hi, 1);
            s_hi += __shfl_xor_sync(0xffffffffu, s_hi, 2);

            l_lo = l_lo * al_lo + s_lo;
            l_hi = l_hi * al_hi + s_hi;
            m_lo = mn_lo;
            m_hi = mn_hi;

#pragma unroll
            for (int na = 0; na < 8; ++na) {
                acc_o[na][0] *= al_lo; acc_o[na][1] *= al_lo;
                acc_o[na][2] *= al_hi; acc_o[na][3] *= al_hi;
            }
        }
        __syncwarp();   // Ss rows are warp-private; make STS visible to LDSM

        // --- Phase C: O += P V  (V natural, trans ldmatrix) ---
#pragma unroll
        for (int ks = 0; ks < 4; ++ks) {
            uint32_t af[4];
            ldsm_x4(af, SS_B + qa_off + ks * 32);
#pragma unroll
            for (int p = 0; p < 4; ++p) {
                uint32_t bq[4];
                ldsm_x4_t(bq, VS_B + vt_off + ks * (16 * APB) + p * 32);
                mma_f16(acc_o[2 * p],     af, &bq[0]);
                mma_f16(acc_o[2 * p + 1], af, &bq[2]);
            }
        }
        // no trailing barrier: next iter's top barrier orders buffer reuse
    }

    // --- epilogue: normalize, write g_attn (half, B,S,D) ---
    {
        const float li_lo = 1.0f / l_lo;
        const float li_hi = 1.0f / l_hi;
        const long r0 = (long)b * S_ + q0 + m0 + g;
#pragma unroll
        for (int na = 0; na < 8; ++na) {
            const int col = h * HD_ + na * 8 + 2 * t4;
            *(__half2*)&g_attn[r0 * D_ + col] =
                __floats2half2_rn(acc_o[na][0] * li_lo, acc_o[na][1] * li_lo);
            *(__half2*)&g_attn[(r0 + 8) * D_ + col] =
                __floats2half2_rn(acc_o[na][2] * li_hi, acc_o[na][3] * li_hi);
        }
    }
}

// ---------------------------------------------------------------------------
// Host launcher (graph-capturable: kernel launches only, no allocs/syncs)
// ---------------------------------------------------------------------------
extern "C" void kernel_launch(void* const* d_in, const int* in_sizes, int n_in,
                              void* d_out, int out_size)
{
    const float* x        = (const float*)d_in[0];
    const float* Wqkv     = (const float*)d_in[1];
    const float* bqkv     = (const float*)d_in[2];
    const float* Wout     = (const float*)d_in[3];
    const float* bout     = (const float*)d_in[4];
    const int*   val_lens = (const int*)d_in[5];
    float* out = (float*)d_out;

    cudaFuncSetAttribute(gemm_h<1>,
                         cudaFuncAttributeMaxDynamicSharedMemorySize, GEMM_SMEM_BYTES);
    cudaFuncSetAttribute(gemm_h<0>,
                         cudaFuncAttributeMaxDynamicSharedMemorySize, GEMM_SMEM_BYTES);
    cudaFuncSetAttribute(attn_h,
                         cudaFuncAttributeMaxDynamicSharedMemorySize, ATTN_SMEM_BYTES);

    // 0) Fused prep: x->half + both weight transposes, one launch
    prep_kernel<<<8192, 256>>>(x, Wqkv, Wout);

    // 1) QKV projection -> half Q/K/V in (B,H,S,HD)
    {
        dim3 grid((3 * D_) / BN, (B_ * S_) / BM);   // 24 x 64
        gemm_h<1><<<grid, 256, GEMM_SMEM_BYTES>>>(bqkv, nullptr, B_ * S_, 3 * D_, D_);
    }
    // 2) Flash attention -> g_attn (half)
    {
        dim3 grid(B_, H_, S_ / QT);                 // batch-fastest
        attn_h<<<grid, 256, ATTN_SMEM_BYTES>>>(val_lens);
    }
    // 3) Output projection -> d_out (fp32 + bias)
    {
        dim3 grid(D_ / BN, (B_ * S_) / BM);         // 8 x 64
        gemm_h<0><<<grid, 256, GEMM_SMEM_BYTES>>>(bout, out, B_ * S_, D_, D_);
    }
}